// round 5
// baseline (speedup 1.0000x reference)
#include <cuda_runtime.h>
#include <cuda_bf16.h>

#define Nn  50000
#define Ee  640000
#define HIDd 128
#define Hh  8
#define Cc  16
#define EFd 16
#define Ll  3
#define DBINS 1024

// ---------------- scratch (static device globals; no allocations) ----------------
__device__ __align__(16) float g_xl[Nn * HIDd];
__device__ __align__(16) float g_xr[Nn * HIDd];
__device__ __align__(16) float g_M[Ll * EFd * HIDd];
__device__ __align__(16) float g_c[Ll * HIDd];
__device__ int g_deg[Nn];
__device__ int g_off[Nn + 1];
__device__ int g_cur[Nn];
__device__ int g_srcS[Ee];                       // src reordered into CSR order
__device__ __align__(16) float g_eaS[Ee * EFd];  // edge_attr reordered into CSR order
__device__ int g_bins[DBINS];
__device__ int g_bincur[DBINS];
__device__ int g_perm[Nn];                       // nodes sorted by degree (desc)

// ---------------- small utility kernels ----------------
__global__ void copy_kernel(const float4* __restrict__ src, float4* __restrict__ dst, int n4) {
    int i = blockIdx.x * blockDim.x + threadIdx.x;
    if (i < n4) dst[i] = src[i];
}

__global__ void zero_deg_kernel(int* __restrict__ deg, int* __restrict__ bins) {
    int i = blockIdx.x * blockDim.x + threadIdx.x;
    if (i < Nn) deg[i] = 0;
    if (i < DBINS) bins[i] = 0;
}

__global__ void hist_kernel(const int* __restrict__ dst, int* __restrict__ deg) {
    int e = blockIdx.x * blockDim.x + threadIdx.x;
    if (e < Ee) atomicAdd(&deg[dst[e]], 1);
}

// single-block exclusive scan over deg -> off, cur ; off[Nn] = Ee
__global__ void scan_kernel(const int* __restrict__ deg, int* __restrict__ off,
                            int* __restrict__ cur) {
    __shared__ int sums[1024];
    const int t = threadIdx.x;
    const int CH = 49;
    int beg = t * CH;
    int local = 0;
#pragma unroll 1
    for (int i = 0; i < CH; i++) {
        int idx = beg + i;
        if (idx < Nn) local += deg[idx];
    }
    sums[t] = local;
    __syncthreads();
    int run = local;
    for (int ofs = 1; ofs < 1024; ofs <<= 1) {
        int u = (t >= ofs) ? sums[t - ofs] : 0;
        __syncthreads();
        run += u;
        sums[t] = run;
        __syncthreads();
    }
    int base = run - local;
#pragma unroll 1
    for (int i = 0; i < CH; i++) {
        int idx = beg + i;
        if (idx < Nn) {
            off[idx] = base;
            cur[idx] = base;
            base += deg[idx];
        }
    }
    if (t == 0) off[Nn] = Ee;
}

// scatter + payload permutation fused: place src and edge_attr into CSR slot
__global__ void scatter_kernel(const int* __restrict__ srcArr, const int* __restrict__ dst,
                               const float* __restrict__ ea,
                               int* __restrict__ cur,
                               int* __restrict__ srcS, float* __restrict__ eaS) {
    int e = blockIdx.x * blockDim.x + threadIdx.x;
    if (e >= Ee) return;
    int p = atomicAdd(&cur[dst[e]], 1);
    srcS[p] = srcArr[e];
    const float4* s4 = (const float4*)(ea + (size_t)e * EFd);
    float4* d4 = (float4*)(eaS + (size_t)p * EFd);
    d4[0] = s4[0]; d4[1] = s4[1]; d4[2] = s4[2]; d4[3] = s4[3];
}

// ------- degree counting-sort (descending) -------
__global__ void hist_deg_kernel(const int* __restrict__ deg, int* __restrict__ bins) {
    int i = blockIdx.x * blockDim.x + threadIdx.x;
    if (i < Nn) {
        int d = deg[i]; if (d > DBINS - 1) d = DBINS - 1;
        atomicAdd(&bins[d], 1);
    }
}

// one block, 1024 threads: bincur[d] = number of nodes with degree > d (descending offsets)
__global__ void scan_bins_kernel(const int* __restrict__ bins, int* __restrict__ bincur) {
    __shared__ int s[DBINS];
    int t = threadIdx.x;
    s[t] = bins[DBINS - 1 - t];   // reversed: s[j] = count of degree (1023-j)
    __syncthreads();
    int v = s[t];
    int run = v;
    for (int ofs = 1; ofs < DBINS; ofs <<= 1) {
        int u = (t >= ofs) ? s[t - ofs] : 0;
        __syncthreads();
        run += u;
        s[t] = run;
        __syncthreads();
    }
    bincur[DBINS - 1 - t] = run - v;  // exclusive prefix of higher degrees
}

__global__ void scatter_perm_kernel(const int* __restrict__ deg, int* __restrict__ bincur,
                                    int* __restrict__ perm) {
    int i = blockIdx.x * blockDim.x + threadIdx.x;
    if (i < Nn) {
        int d = deg[i]; if (d > DBINS - 1) d = DBINS - 1;
        int p = atomicAdd(&bincur[d], 1);
        perm[p] = i;
    }
}

// M[l] = Wt(16x128) @ We[l](128x128); c[l] = bt @ We[l]
__global__ void precompute_kernel(const float* __restrict__ Wt, const float* __restrict__ bt,
                                  const float* __restrict__ We,
                                  float* __restrict__ M, float* __restrict__ cv) {
    int l = blockIdx.x;
    int j = threadIdx.x;
    const float* Wel = We + l * HIDd * HIDd;
    float acc[EFd];
#pragma unroll
    for (int k = 0; k < EFd; k++) acc[k] = 0.f;
    float cacc = 0.f;
    for (int i = 0; i < HIDd; i++) {
        float w = Wel[i * HIDd + j];
        cacc = fmaf(bt[i], w, cacc);
#pragma unroll
        for (int k = 0; k < EFd; k++) acc[k] = fmaf(Wt[k * HIDd + i], w, acc[k]);
    }
#pragma unroll
    for (int k = 0; k < EFd; k++) M[l * EFd * HIDd + k * HIDd + j] = acc[k];
    cv[l * HIDd + j] = cacc;
}

// ---------------- SGEMM: C[nrows,128] = A[nrows,128] @ W[128,128] + bias ----------------
__global__ void __launch_bounds__(256, 2) gemm128x2(const float* __restrict__ A,
                                                    const float* __restrict__ W0,
                                                    const float* __restrict__ b0,
                                                    float* __restrict__ C0,
                                                    const float* __restrict__ W1,
                                                    const float* __restrict__ b1,
                                                    float* __restrict__ C1,
                                                    int nrows) {
    const float* W    = blockIdx.y ? W1 : W0;
    const float* bias = blockIdx.y ? b1 : b0;
    float*       C    = blockIdx.y ? C1 : C0;

    __shared__ __align__(16) float As[32][132];
    __shared__ __align__(16) float Bs[32][128];
    const int tid = threadIdx.x;
    const int tn = (tid & 15) * 8;
    const int tm = (tid >> 4) * 8;
    const int rowBase = blockIdx.x * 128;

    float acc[8][8];
#pragma unroll
    for (int i = 0; i < 8; i++)
#pragma unroll
        for (int j = 0; j < 8; j++) acc[i][j] = 0.f;

    const int ar = tid >> 3;
    const int ak = (tid & 7) << 2;
    const int bk = tid >> 5;
    const int bn = (tid & 31) << 2;

    for (int kc = 0; kc < 128; kc += 32) {
#pragma unroll
        for (int q = 0; q < 4; q++) {
            int r = ar + q * 32;
            int gr = rowBase + r;
            float4 v = make_float4(0.f, 0.f, 0.f, 0.f);
            if (gr < nrows) v = *(const float4*)(A + (size_t)gr * HIDd + kc + ak);
            As[ak + 0][r] = v.x; As[ak + 1][r] = v.y;
            As[ak + 2][r] = v.z; As[ak + 3][r] = v.w;
        }
#pragma unroll
        for (int q = 0; q < 4; q++) {
            int r = bk + q * 8;
            *(float4*)&Bs[r][bn] = *(const float4*)(W + (size_t)(kc + r) * HIDd + bn);
        }
        __syncthreads();
#pragma unroll
        for (int kk = 0; kk < 32; kk++) {
            float a[8], b[8];
            *(float4*)(a)     = *(const float4*)&As[kk][tm];
            *(float4*)(a + 4) = *(const float4*)&As[kk][tm + 4];
            *(float4*)(b)     = *(const float4*)&Bs[kk][tn];
            *(float4*)(b + 4) = *(const float4*)&Bs[kk][tn + 4];
#pragma unroll
            for (int i = 0; i < 8; i++)
#pragma unroll
                for (int j = 0; j < 8; j++) acc[i][j] = fmaf(a[i], b[j], acc[i][j]);
        }
        __syncthreads();
    }

    float bb[8];
#pragma unroll
    for (int j = 0; j < 8; j++) bb[j] = bias[tn + j];
#pragma unroll
    for (int i = 0; i < 8; i++) {
        int gr = rowBase + tm + i;
        if (gr < nrows) {
            float4 o;
            o.x = acc[i][0] + bb[0]; o.y = acc[i][1] + bb[1];
            o.z = acc[i][2] + bb[2]; o.w = acc[i][3] + bb[3];
            *(float4*)(C + (size_t)gr * HIDd + tn) = o;
            o.x = acc[i][4] + bb[4]; o.y = acc[i][5] + bb[5];
            o.z = acc[i][6] + bb[6]; o.w = acc[i][7] + bb[7];
            *(float4*)(C + (size_t)gr * HIDd + tn + 4) = o;
        }
    }
}

// ---------------- fused node pass: one warp per dst node (degree-sorted) ----------------
__global__ void __launch_bounds__(256) node_kernel(const float* __restrict__ eaS,
                                                   const int* __restrict__ srcS,
                                                   const float* __restrict__ xl,
                                                   const float* __restrict__ xr,
                                                   const int* __restrict__ off,
                                                   const int* __restrict__ perm,
                                                   const float* __restrict__ M,
                                                   const float* __restrict__ cvec,
                                                   const float* __restrict__ att,
                                                   const float* __restrict__ bias_o,
                                                   const float* __restrict__ lng,
                                                   const float* __restrict__ lnb,
                                                   float* __restrict__ x) {
    __shared__ __align__(16) float sM[EFd * HIDd];
    __shared__ __align__(16) float sC[HIDd];
    __shared__ __align__(16) float sA[HIDd];
    const int tid = threadIdx.x;
    for (int i = tid; i < EFd * HIDd; i += 256) sM[i] = M[i];
    if (tid < HIDd) {
        sC[tid] = cvec[tid];
        sA[tid] = att[tid] * 1.4426950408889634f;  // exp(x)=exp2(x*log2e)
    }
    __syncthreads();

    const int gw = (blockIdx.x * 256 + tid) >> 5;
    const int lane = tid & 31;
    if (gw >= Nn) return;
    const int n = perm[gw];

    const int beg = off[n];
    const int end = off[n + 1];

    const float4 xrv = ((const float4*)xr)[(size_t)n * 32 + lane];
    const float4 cv4 = ((const float4*)sC)[lane];
    const float4 av  = ((const float4*)sA)[lane];
    const float4* sM4 = (const float4*)sM;

    float4 acc = make_float4(0.f, 0.f, 0.f, 0.f);
    float dsum = 0.f;

    // pipeline registers: each lane holds the FULL 16-float ea row (uniform LDG, no shfl)
    float4 ea0[4];
    float4 xlv0 = make_float4(0.f, 0.f, 0.f, 0.f);
    if (beg < end) {
        const float4* r4 = (const float4*)(eaS + (size_t)beg * EFd);
        ea0[0] = r4[0]; ea0[1] = r4[1]; ea0[2] = r4[2]; ea0[3] = r4[3];
        int s0 = srcS[beg];
        xlv0 = ((const float4*)xl)[(size_t)s0 * 32 + lane];
    }

    for (int i = beg; i < end; i++) {
        float4 ea1[4];
        float4 xlv1;
        ea1[0] = ea0[0]; ea1[1] = ea0[1]; ea1[2] = ea0[2]; ea1[3] = ea0[3];
        xlv1 = xlv0;
        if (i + 1 < end) {
            const float4* r4 = (const float4*)(eaS + (size_t)(i + 1) * EFd);
            ea1[0] = r4[0]; ea1[1] = r4[1]; ea1[2] = r4[2]; ea1[3] = r4[3];
            int s1 = srcS[i + 1];
            xlv1 = ((const float4*)xl)[(size_t)s1 * 32 + lane];
        }

        float a[16];
        *(float4*)&a[0]  = ea0[0];
        *(float4*)&a[4]  = ea0[1];
        *(float4*)&a[8]  = ea0[2];
        *(float4*)&a[12] = ea0[3];
        const float4 xlv = xlv0;

        // em = c + ea(16) @ M(16x128), two independent 8-deep chains
        float4 emA = cv4;
        float4 emB = make_float4(0.f, 0.f, 0.f, 0.f);
#pragma unroll
        for (int k = 0; k < 8; k++) {
            float4 mv = sM4[k * 32 + lane];
            emA.x = fmaf(a[k], mv.x, emA.x);
            emA.y = fmaf(a[k], mv.y, emA.y);
            emA.z = fmaf(a[k], mv.z, emA.z);
            emA.w = fmaf(a[k], mv.w, emA.w);
        }
#pragma unroll
        for (int k = 8; k < 16; k++) {
            float4 mv = sM4[k * 32 + lane];
            emB.x = fmaf(a[k], mv.x, emB.x);
            emB.y = fmaf(a[k], mv.y, emB.y);
            emB.z = fmaf(a[k], mv.z, emB.z);
            emB.w = fmaf(a[k], mv.w, emB.w);
        }
        float4 m;
        m.x = xlv.x + xrv.x + emA.x + emB.x;
        m.y = xlv.y + xrv.y + emA.y + emB.y;
        m.z = xlv.z + xrv.z + emA.z + emB.z;
        m.w = xlv.w + xrv.w + emA.w + emB.w;
        m.x = (m.x > 0.f) ? m.x : 0.2f * m.x;
        m.y = (m.y > 0.f) ? m.y : 0.2f * m.y;
        m.z = (m.z > 0.f) ? m.z : 0.2f * m.z;
        m.w = (m.w > 0.f) ? m.w : 0.2f * m.w;

        float part = m.x * av.x + m.y * av.y + m.z * av.z + m.w * av.w;
        part += __shfl_xor_sync(0xffffffffu, part, 1);
        part += __shfl_xor_sync(0xffffffffu, part, 2);  // logit*log2e for head lane>>2

        float p = exp2f(part);
        dsum += p;
        acc.x = fmaf(p, xlv.x, acc.x);
        acc.y = fmaf(p, xlv.y, acc.y);
        acc.z = fmaf(p, xlv.z, acc.z);
        acc.w = fmaf(p, xlv.w, acc.w);

        ea0[0] = ea1[0]; ea0[1] = ea1[1]; ea0[2] = ea1[2]; ea0[3] = ea1[3];
        xlv0 = xlv1;
    }

    const float inv = 1.0f / (dsum + 1e-16f);
    float4 bo = ((const float4*)bias_o)[lane];
    float4 o;
    o.x = acc.x * inv + bo.x;
    o.y = acc.y * inv + bo.y;
    o.z = acc.z * inv + bo.z;
    o.w = acc.w * inv + bo.w;

    float s  = o.x + o.y + o.z + o.w;
    float sq = o.x * o.x + o.y * o.y + o.z * o.z + o.w * o.w;
#pragma unroll
    for (int ofs = 16; ofs > 0; ofs >>= 1) {
        s  += __shfl_xor_sync(0xffffffffu, s, ofs);
        sq += __shfl_xor_sync(0xffffffffu, sq, ofs);
    }
    float mu   = s * (1.0f / 128.0f);
    float var  = sq * (1.0f / 128.0f) - mu * mu;
    float rstd = rsqrtf(var + 1e-5f);

    float4 gv = ((const float4*)lng)[lane];
    float4 bv = ((const float4*)lnb)[lane];
    float4 xv = ((float4*)x)[(size_t)n * 32 + lane];
    float y;
    y = gv.x * (o.x - mu) * rstd + bv.x; xv.x += fmaxf(y, 0.f);
    y = gv.y * (o.y - mu) * rstd + bv.y; xv.y += fmaxf(y, 0.f);
    y = gv.z * (o.z - mu) * rstd + bv.z; xv.z += fmaxf(y, 0.f);
    y = gv.w * (o.w - mu) * rstd + bv.w; xv.w += fmaxf(y, 0.f);
    ((float4*)x)[(size_t)n * 32 + lane] = xv;
}

// ---------------- launch ----------------
extern "C" void kernel_launch(void* const* d_in, const int* in_sizes, int n_in,
                              void* d_out, int out_size) {
    const float* x   = (const float*)d_in[0];
    const int*   ei  = (const int*)d_in[2];
    const float* ea  = (const float*)d_in[3];
    const float* Wt  = (const float*)d_in[4];
    const float* bt  = (const float*)d_in[5];
    const float* Wl  = (const float*)d_in[6];
    const float* bl  = (const float*)d_in[7];
    const float* Wr  = (const float*)d_in[8];
    const float* br  = (const float*)d_in[9];
    const float* We  = (const float*)d_in[10];
    const float* att = (const float*)d_in[11];
    const float* bo  = (const float*)d_in[12];
    const float* lg  = (const float*)d_in[13];
    const float* lb  = (const float*)d_in[14];
    float* xbuf = (float*)d_out;

    float *pxl, *pxr, *pM, *pc, *peaS;
    int *pdeg, *poff, *pcur, *psrcS, *pbins, *pbincur, *pperm;
    cudaGetSymbolAddress((void**)&pxl,     g_xl);
    cudaGetSymbolAddress((void**)&pxr,     g_xr);
    cudaGetSymbolAddress((void**)&pM,      g_M);
    cudaGetSymbolAddress((void**)&pc,      g_c);
    cudaGetSymbolAddress((void**)&pdeg,    g_deg);
    cudaGetSymbolAddress((void**)&poff,    g_off);
    cudaGetSymbolAddress((void**)&pcur,    g_cur);
    cudaGetSymbolAddress((void**)&psrcS,   g_srcS);
    cudaGetSymbolAddress((void**)&peaS,    g_eaS);
    cudaGetSymbolAddress((void**)&pbins,   g_bins);
    cudaGetSymbolAddress((void**)&pbincur, g_bincur);
    cudaGetSymbolAddress((void**)&pperm,   g_perm);

    const int* srcArr = ei;
    const int* dstArr = ei + Ee;
    const int n4x = Nn * 32;

    copy_kernel<<<(n4x + 255) / 256, 256>>>((const float4*)x, (float4*)xbuf, n4x);
    precompute_kernel<<<Ll, HIDd>>>(Wt, bt, We, pM, pc);

    // CSR build + payload permutation + degree sort (once per launch)
    zero_deg_kernel<<<(Nn + 255) / 256, 256>>>(pdeg, pbins);
    hist_kernel<<<(Ee + 255) / 256, 256>>>(dstArr, pdeg);
    scan_kernel<<<1, 1024>>>(pdeg, poff, pcur);
    scatter_kernel<<<(Ee + 255) / 256, 256>>>(srcArr, dstArr, ea, pcur, psrcS, peaS);
    hist_deg_kernel<<<(Nn + 255) / 256, 256>>>(pdeg, pbins);
    scan_bins_kernel<<<1, DBINS>>>(pbins, pbincur);
    scatter_perm_kernel<<<(Nn + 255) / 256, 256>>>(pdeg, pbincur, pperm);

    dim3 ggrid((Nn + 127) / 128, 2);
    for (int l = 0; l < Ll; l++) {
        gemm128x2<<<ggrid, 256>>>(xbuf,
                                  Wl + (size_t)l * HIDd * HIDd, bl + l * HIDd, pxl,
                                  Wr + (size_t)l * HIDd * HIDd, br + l * HIDd, pxr, Nn);
        node_kernel<<<(Nn * 32 + 255) / 256, 256>>>(peaS, psrcS, pxl, pxr, poff, pperm,
                                                    pM + (size_t)l * EFd * HIDd, pc + l * HIDd,
                                                    att + l * HIDd, bo + l * HIDd,
                                                    lg + l * HIDd, lb + l * HIDd, xbuf);
    }
}

// round 6
// speedup vs baseline: 1.2156x; 1.2156x over previous
#include <cuda_runtime.h>
#include <cuda_bf16.h>

#define Nn  50000
#define Ee  640000
#define HIDd 128
#define Hh  8
#define Cc  16
#define EFd 16
#define Ll  3
#define DBINS 1024

typedef unsigned long long u64;

// ---------------- scratch (static device globals; no allocations) ----------------
__device__ __align__(16) float g_xl[Nn * HIDd];
__device__ __align__(16) float g_xr[Nn * HIDd];
__device__ __align__(16) float g_M[Ll * EFd * HIDd];
__device__ __align__(16) float g_c[Ll * HIDd];
__device__ int g_deg[Nn];
__device__ int g_off[Nn + 1];
__device__ int g_cur[Nn];
__device__ int g_srcS[Ee];                      // src reordered into CSR order
__device__ __align__(16) u64 g_eaD[Ee * EFd];   // edge_attr in CSR order, duplicated (a,a) pairs
__device__ int g_bins[DBINS];
__device__ int g_bincur[DBINS];
__device__ int g_perm[Nn];                      // nodes sorted by degree (desc)

// ---------------- f32x2 helpers (sm_103a packed fp32) ----------------
__device__ __forceinline__ u64 pk2(float a, float b) {
    u64 r; asm("mov.b64 %0, {%1, %2};" : "=l"(r) : "f"(a), "f"(b)); return r;
}
__device__ __forceinline__ void upk2(float& a, float& b, u64 v) {
    asm("mov.b64 {%0, %1}, %2;" : "=f"(a), "=f"(b) : "l"(v));
}
__device__ __forceinline__ u64 fma2(u64 a, u64 b, u64 c) {
    u64 d; asm("fma.rn.f32x2 %0, %1, %2, %3;" : "=l"(d) : "l"(a), "l"(b), "l"(c)); return d;
}
__device__ __forceinline__ u64 add2(u64 a, u64 b) {
    u64 d; asm("add.rn.f32x2 %0, %1, %2;" : "=l"(d) : "l"(a), "l"(b)); return d;
}
__device__ __forceinline__ float ex2(float x) {
    float y; asm("ex2.approx.ftz.f32 %0, %1;" : "=f"(y) : "f"(x)); return y;
}

// ---------------- small utility kernels ----------------
__global__ void copy_kernel(const float4* __restrict__ src, float4* __restrict__ dst, int n4) {
    int i = blockIdx.x * blockDim.x + threadIdx.x;
    if (i < n4) dst[i] = src[i];
}

__global__ void zero_deg_kernel(int* __restrict__ deg, int* __restrict__ bins) {
    int i = blockIdx.x * blockDim.x + threadIdx.x;
    if (i < Nn) deg[i] = 0;
    if (i < DBINS) bins[i] = 0;
}

__global__ void hist_kernel(const int* __restrict__ dst, int* __restrict__ deg) {
    int e = blockIdx.x * blockDim.x + threadIdx.x;
    if (e < Ee) atomicAdd(&deg[dst[e]], 1);
}

// single-block exclusive scan over deg -> off, cur ; off[Nn] = Ee
__global__ void scan_kernel(const int* __restrict__ deg, int* __restrict__ off,
                            int* __restrict__ cur) {
    __shared__ int sums[1024];
    const int t = threadIdx.x;
    const int CH = 49;
    int beg = t * CH;
    int local = 0;
#pragma unroll 1
    for (int i = 0; i < CH; i++) {
        int idx = beg + i;
        if (idx < Nn) local += deg[idx];
    }
    sums[t] = local;
    __syncthreads();
    int run = local;
    for (int ofs = 1; ofs < 1024; ofs <<= 1) {
        int u = (t >= ofs) ? sums[t - ofs] : 0;
        __syncthreads();
        run += u;
        sums[t] = run;
        __syncthreads();
    }
    int base = run - local;
#pragma unroll 1
    for (int i = 0; i < CH; i++) {
        int idx = beg + i;
        if (idx < Nn) {
            off[idx] = base;
            cur[idx] = base;
            base += deg[idx];
        }
    }
    if (t == 0) off[Nn] = Ee;
}

// scatter fused with payload permutation: src + duplicated-pair edge_attr into CSR slot
__global__ void scatter_kernel(const int* __restrict__ srcArr, const int* __restrict__ dst,
                               const float* __restrict__ ea,
                               int* __restrict__ cur,
                               int* __restrict__ srcS, u64* __restrict__ eaD) {
    int e = blockIdx.x * blockDim.x + threadIdx.x;
    if (e >= Ee) return;
    int p = atomicAdd(&cur[dst[e]], 1);
    srcS[p] = srcArr[e];
    const float4* s4 = (const float4*)(ea + (size_t)e * EFd);
    ulonglong2* d2 = (ulonglong2*)(eaD + (size_t)p * EFd);
#pragma unroll
    for (int j = 0; j < 4; j++) {
        float4 v = s4[j];
        ulonglong2 o0; o0.x = pk2(v.x, v.x); o0.y = pk2(v.y, v.y);
        ulonglong2 o1; o1.x = pk2(v.z, v.z); o1.y = pk2(v.w, v.w);
        d2[j * 2 + 0] = o0;
        d2[j * 2 + 1] = o1;
    }
}

// ------- degree counting-sort (descending) -------
__global__ void hist_deg_kernel(const int* __restrict__ deg, int* __restrict__ bins) {
    int i = blockIdx.x * blockDim.x + threadIdx.x;
    if (i < Nn) {
        int d = deg[i]; if (d > DBINS - 1) d = DBINS - 1;
        atomicAdd(&bins[d], 1);
    }
}

__global__ void scan_bins_kernel(const int* __restrict__ bins, int* __restrict__ bincur) {
    __shared__ int s[DBINS];
    int t = threadIdx.x;
    s[t] = bins[DBINS - 1 - t];
    __syncthreads();
    int v = s[t];
    int run = v;
    for (int ofs = 1; ofs < DBINS; ofs <<= 1) {
        int u = (t >= ofs) ? s[t - ofs] : 0;
        __syncthreads();
        run += u;
        s[t] = run;
        __syncthreads();
    }
    bincur[DBINS - 1 - t] = run - v;
}

__global__ void scatter_perm_kernel(const int* __restrict__ deg, int* __restrict__ bincur,
                                    int* __restrict__ perm) {
    int i = blockIdx.x * blockDim.x + threadIdx.x;
    if (i < Nn) {
        int d = deg[i]; if (d > DBINS - 1) d = DBINS - 1;
        int p = atomicAdd(&bincur[d], 1);
        perm[p] = i;
    }
}

// M[l] = Wt(16x128) @ We[l](128x128); c[l] = bt @ We[l]
__global__ void precompute_kernel(const float* __restrict__ Wt, const float* __restrict__ bt,
                                  const float* __restrict__ We,
                                  float* __restrict__ M, float* __restrict__ cv) {
    int l = blockIdx.x;
    int j = threadIdx.x;
    const float* Wel = We + l * HIDd * HIDd;
    float acc[EFd];
#pragma unroll
    for (int k = 0; k < EFd; k++) acc[k] = 0.f;
    float cacc = 0.f;
    for (int i = 0; i < HIDd; i++) {
        float w = Wel[i * HIDd + j];
        cacc = fmaf(bt[i], w, cacc);
#pragma unroll
        for (int k = 0; k < EFd; k++) acc[k] = fmaf(Wt[k * HIDd + i], w, acc[k]);
    }
#pragma unroll
    for (int k = 0; k < EFd; k++) M[l * EFd * HIDd + k * HIDd + j] = acc[k];
    cv[l * HIDd + j] = cacc;
}

// ---------------- SGEMM: C[nrows,128] = A[nrows,128] @ W[128,128] + bias ----------------
__global__ void __launch_bounds__(256, 2) gemm128x2(const float* __restrict__ A,
                                                    const float* __restrict__ W0,
                                                    const float* __restrict__ b0,
                                                    float* __restrict__ C0,
                                                    const float* __restrict__ W1,
                                                    const float* __restrict__ b1,
                                                    float* __restrict__ C1,
                                                    int nrows) {
    const float* W    = blockIdx.y ? W1 : W0;
    const float* bias = blockIdx.y ? b1 : b0;
    float*       C    = blockIdx.y ? C1 : C0;

    __shared__ __align__(16) float As[32][132];
    __shared__ __align__(16) float Bs[32][128];
    const int tid = threadIdx.x;
    const int tn = (tid & 15) * 8;
    const int tm = (tid >> 4) * 8;
    const int rowBase = blockIdx.x * 128;

    float acc[8][8];
#pragma unroll
    for (int i = 0; i < 8; i++)
#pragma unroll
        for (int j = 0; j < 8; j++) acc[i][j] = 0.f;

    const int ar = tid >> 3;
    const int ak = (tid & 7) << 2;
    const int bk = tid >> 5;
    const int bn = (tid & 31) << 2;

    for (int kc = 0; kc < 128; kc += 32) {
#pragma unroll
        for (int q = 0; q < 4; q++) {
            int r = ar + q * 32;
            int gr = rowBase + r;
            float4 v = make_float4(0.f, 0.f, 0.f, 0.f);
            if (gr < nrows) v = *(const float4*)(A + (size_t)gr * HIDd + kc + ak);
            As[ak + 0][r] = v.x; As[ak + 1][r] = v.y;
            As[ak + 2][r] = v.z; As[ak + 3][r] = v.w;
        }
#pragma unroll
        for (int q = 0; q < 4; q++) {
            int r = bk + q * 8;
            *(float4*)&Bs[r][bn] = *(const float4*)(W + (size_t)(kc + r) * HIDd + bn);
        }
        __syncthreads();
#pragma unroll
        for (int kk = 0; kk < 32; kk++) {
            float a[8], b[8];
            *(float4*)(a)     = *(const float4*)&As[kk][tm];
            *(float4*)(a + 4) = *(const float4*)&As[kk][tm + 4];
            *(float4*)(b)     = *(const float4*)&Bs[kk][tn];
            *(float4*)(b + 4) = *(const float4*)&Bs[kk][tn + 4];
#pragma unroll
            for (int i = 0; i < 8; i++)
#pragma unroll
                for (int j = 0; j < 8; j++) acc[i][j] = fmaf(a[i], b[j], acc[i][j]);
        }
        __syncthreads();
    }

    float bb[8];
#pragma unroll
    for (int j = 0; j < 8; j++) bb[j] = bias[tn + j];
#pragma unroll
    for (int i = 0; i < 8; i++) {
        int gr = rowBase + tm + i;
        if (gr < nrows) {
            float4 o;
            o.x = acc[i][0] + bb[0]; o.y = acc[i][1] + bb[1];
            o.z = acc[i][2] + bb[2]; o.w = acc[i][3] + bb[3];
            *(float4*)(C + (size_t)gr * HIDd + tn) = o;
            o.x = acc[i][4] + bb[4]; o.y = acc[i][5] + bb[5];
            o.z = acc[i][6] + bb[6]; o.w = acc[i][7] + bb[7];
            *(float4*)(C + (size_t)gr * HIDd + tn + 4) = o;
        }
    }
}

// ---------------- fused node pass: one warp per dst node (degree-sorted) ----------------
// M held in registers (16 x ulonglong2 per lane); ea read as duplicated u64 pairs
// (uniform LDG.64 per k, no shfl); em chain in f32x2; no shared memory.
__global__ void __launch_bounds__(256, 2) node_kernel(const u64* __restrict__ eaD,
                                                      const int* __restrict__ srcS,
                                                      const float* __restrict__ xl,
                                                      const float* __restrict__ xr,
                                                      const int* __restrict__ off,
                                                      const int* __restrict__ perm,
                                                      const float* __restrict__ M,
                                                      const float* __restrict__ cvec,
                                                      const float* __restrict__ att,
                                                      const float* __restrict__ bias_o,
                                                      const float* __restrict__ lng,
                                                      const float* __restrict__ lnb,
                                                      float* __restrict__ x) {
    const int tid = threadIdx.x;
    const int gw = (blockIdx.x * 256 + tid) >> 5;
    const int lane = tid & 31;
    if (gw >= Nn) return;
    const int n = perm[gw];

    // per-lane slice of M: rows k=0..15, channels lane*4..lane*4+3, as 2 packed pairs
    ulonglong2 Mk[EFd];
    {
        const ulonglong2* M2 = (const ulonglong2*)M;
#pragma unroll
        for (int k = 0; k < EFd; k++) Mk[k] = M2[k * 32 + lane];
    }

    const int beg = off[n];
    const int end = off[n + 1];

    const float4 xrv = ((const float4*)xr)[(size_t)n * 32 + lane];
    const float4 cv4 = ((const float4*)cvec)[lane];
    float4 av = ((const float4*)att)[lane];
    const float L2E = 1.4426950408889634f;  // exp(x) = exp2(x*log2e)
    av.x *= L2E; av.y *= L2E; av.z *= L2E; av.w *= L2E;

    // loop-invariant: pre = xr + c
    float4 pre;
    pre.x = xrv.x + cv4.x; pre.y = xrv.y + cv4.y;
    pre.z = xrv.z + cv4.z; pre.w = xrv.w + cv4.w;

    float4 acc = make_float4(0.f, 0.f, 0.f, 0.f);
    float dsum = 0.f;

    float4 xlv0 = make_float4(0.f, 0.f, 0.f, 0.f);
    if (beg < end) {
        int s0 = srcS[beg];
        xlv0 = ((const float4*)xl)[(size_t)s0 * 32 + lane];
    }

    for (int i = beg; i < end; i++) {
        float4 xlv1 = xlv0;
        if (i + 1 < end) {
            int s1 = srcS[i + 1];
            xlv1 = ((const float4*)xl)[(size_t)s1 * 32 + lane];
        }
        const float4 xlv = xlv0;

        const u64* ed = eaD + (size_t)i * EFd;  // uniform across lanes
        u64 emA01 = 0, emA23 = 0, emB01 = 0, emB23 = 0;
#pragma unroll
        for (int k = 0; k < 8; k++) {
            u64 aa = ed[k];
            emA01 = fma2(aa, Mk[k].x, emA01);
            emA23 = fma2(aa, Mk[k].y, emA23);
        }
#pragma unroll
        for (int k = 8; k < 16; k++) {
            u64 aa = ed[k];
            emB01 = fma2(aa, Mk[k].x, emB01);
            emB23 = fma2(aa, Mk[k].y, emB23);
        }
        u64 em01 = add2(emA01, emB01);
        u64 em23 = add2(emA23, emB23);
        float e0, e1, e2, e3;
        upk2(e0, e1, em01);
        upk2(e2, e3, em23);

        float m0 = xlv.x + pre.x + e0;
        float m1 = xlv.y + pre.y + e1;
        float m2 = xlv.z + pre.z + e2;
        float m3 = xlv.w + pre.w + e3;
        m0 = fmaxf(m0, 0.2f * m0);   // leaky-relu
        m1 = fmaxf(m1, 0.2f * m1);
        m2 = fmaxf(m2, 0.2f * m2);
        m3 = fmaxf(m3, 0.2f * m3);

        float part = m0 * av.x + m1 * av.y + m2 * av.z + m3 * av.w;
        part += __shfl_xor_sync(0xffffffffu, part, 1);
        part += __shfl_xor_sync(0xffffffffu, part, 2);  // logit*log2e for head = lane>>2

        float p = ex2(part);
        dsum += p;
        acc.x = fmaf(p, xlv.x, acc.x);
        acc.y = fmaf(p, xlv.y, acc.y);
        acc.z = fmaf(p, xlv.z, acc.z);
        acc.w = fmaf(p, xlv.w, acc.w);

        xlv0 = xlv1;
    }

    const float inv = 1.0f / (dsum + 1e-16f);
    float4 bo = ((const float4*)bias_o)[lane];
    float4 o;
    o.x = acc.x * inv + bo.x;
    o.y = acc.y * inv + bo.y;
    o.z = acc.z * inv + bo.z;
    o.w = acc.w * inv + bo.w;

    float s  = o.x + o.y + o.z + o.w;
    float sq = o.x * o.x + o.y * o.y + o.z * o.z + o.w * o.w;
#pragma unroll
    for (int ofs = 16; ofs > 0; ofs >>= 1) {
        s  += __shfl_xor_sync(0xffffffffu, s, ofs);
        sq += __shfl_xor_sync(0xffffffffu, sq, ofs);
    }
    float mu   = s * (1.0f / 128.0f);
    float var  = sq * (1.0f / 128.0f) - mu * mu;
    float rstd = rsqrtf(var + 1e-5f);

    float4 gv = ((const float4*)lng)[lane];
    float4 bv = ((const float4*)lnb)[lane];
    float4 xv = ((float4*)x)[(size_t)n * 32 + lane];
    float y;
    y = gv.x * (o.x - mu) * rstd + bv.x; xv.x += fmaxf(y, 0.f);
    y = gv.y * (o.y - mu) * rstd + bv.y; xv.y += fmaxf(y, 0.f);
    y = gv.z * (o.z - mu) * rstd + bv.z; xv.z += fmaxf(y, 0.f);
    y = gv.w * (o.w - mu) * rstd + bv.w; xv.w += fmaxf(y, 0.f);
    ((float4*)x)[(size_t)n * 32 + lane] = xv;
}

// ---------------- launch ----------------
extern "C" void kernel_launch(void* const* d_in, const int* in_sizes, int n_in,
                              void* d_out, int out_size) {
    const float* x   = (const float*)d_in[0];
    const int*   ei  = (const int*)d_in[2];
    const float* ea  = (const float*)d_in[3];
    const float* Wt  = (const float*)d_in[4];
    const float* bt  = (const float*)d_in[5];
    const float* Wl  = (const float*)d_in[6];
    const float* bl  = (const float*)d_in[7];
    const float* Wr  = (const float*)d_in[8];
    const float* br  = (const float*)d_in[9];
    const float* We  = (const float*)d_in[10];
    const float* att = (const float*)d_in[11];
    const float* bo  = (const float*)d_in[12];
    const float* lg  = (const float*)d_in[13];
    const float* lb  = (const float*)d_in[14];
    float* xbuf = (float*)d_out;

    float *pxl, *pxr, *pM, *pc;
    u64* peaD;
    int *pdeg, *poff, *pcur, *psrcS, *pbins, *pbincur, *pperm;
    cudaGetSymbolAddress((void**)&pxl,     g_xl);
    cudaGetSymbolAddress((void**)&pxr,     g_xr);
    cudaGetSymbolAddress((void**)&pM,      g_M);
    cudaGetSymbolAddress((void**)&pc,      g_c);
    cudaGetSymbolAddress((void**)&pdeg,    g_deg);
    cudaGetSymbolAddress((void**)&poff,    g_off);
    cudaGetSymbolAddress((void**)&pcur,    g_cur);
    cudaGetSymbolAddress((void**)&psrcS,   g_srcS);
    cudaGetSymbolAddress((void**)&peaD,    g_eaD);
    cudaGetSymbolAddress((void**)&pbins,   g_bins);
    cudaGetSymbolAddress((void**)&pbincur, g_bincur);
    cudaGetSymbolAddress((void**)&pperm,   g_perm);

    const int* srcArr = ei;
    const int* dstArr = ei + Ee;
    const int n4x = Nn * 32;

    copy_kernel<<<(n4x + 255) / 256, 256>>>((const float4*)x, (float4*)xbuf, n4x);
    precompute_kernel<<<Ll, HIDd>>>(Wt, bt, We, pM, pc);

    // CSR build + payload permutation + degree sort (once per launch)
    zero_deg_kernel<<<(Nn + 255) / 256, 256>>>(pdeg, pbins);
    hist_kernel<<<(Ee + 255) / 256, 256>>>(dstArr, pdeg);
    scan_kernel<<<1, 1024>>>(pdeg, poff, pcur);
    scatter_kernel<<<(Ee + 255) / 256, 256>>>(srcArr, dstArr, ea, pcur, psrcS, peaD);
    hist_deg_kernel<<<(Nn + 255) / 256, 256>>>(pdeg, pbins);
    scan_bins_kernel<<<1, DBINS>>>(pbins, pbincur);
    scatter_perm_kernel<<<(Nn + 255) / 256, 256>>>(pdeg, pbincur, pperm);

    dim3 ggrid((Nn + 127) / 128, 2);
    for (int l = 0; l < Ll; l++) {
        gemm128x2<<<ggrid, 256>>>(xbuf,
                                  Wl + (size_t)l * HIDd * HIDd, bl + l * HIDd, pxl,
                                  Wr + (size_t)l * HIDd * HIDd, br + l * HIDd, pxr, Nn);
        node_kernel<<<(Nn * 32 + 255) / 256, 256>>>(peaD, psrcS, pxl, pxr, poff, pperm,
                                                    pM + (size_t)l * EFd * HIDd, pc + l * HIDd,
                                                    att + l * HIDd, bo + l * HIDd,
                                                    lg + l * HIDd, lb + l * HIDd, xbuf);
    }
}